// round 10
// baseline (speedup 1.0000x reference)
#include <cuda_runtime.h>
#include <cuda_fp16.h>
#include <cstdint>

// ---------------------------------------------------------------------------
// VQVAE forward on sm_103 (baseline PTX: ldmatrix + mma.sync fp16).
//   z_e = x @ W_enc^T + b_enc  via scaled fp16-split HMMA (fp32 accum)
//     A scaled 2^8, B scaled 2^10 -> residuals stay fp16-normal.
//     z tiles   (cols  0.. 95): 1 product  (hh)              ~1.4e-4 rel err
//                               (feeds only the loss mean -> bias << 1e-3)
//     dot tiles (cols 96..127): 3 products (hh + lh + hl)    fp32-level
//   argmin / loss  : in-register epilogue + quad shfl reduce
//   x_recon        : fused coalesced gather from precomputed 21x1024 table
//   x loads        : register-prefetched one chunk ahead (hidden behind MMA)
// ---------------------------------------------------------------------------

#define NCODES 21
#define LDIM   100
#define IDIM   1024
#define NPAD   128
#define CTA_M  128
#define KC     64
#define NCHUNK (IDIM / KC)
#define NT     16

#define ASCALE 256.0f                 // 2^8
#define BSCALE 1024.0f                // 2^10
#define INVS   3.814697265625e-06f    // 2^-18

__device__ __half g_Bh[NPAD * IDIM];
__device__ __half g_Bl[NPAD * IDIM];
__device__ float  g_recon[NCODES * IDIM];
__device__ float  g_ck[NCODES];            // ||c_k||^2 - 2 b.c_k
__device__ double g_loss;

__device__ __forceinline__ uint32_t smem_u32(const void* p) {
    uint32_t a;
    asm("{ .reg .u64 t; cvta.to.shared.u64 t, %1; cvt.u32.u64 %0, t; }"
        : "=r"(a) : "l"(p));
    return a;
}
__device__ __forceinline__ uint32_t pack_f16x2(float a, float b) {
    uint32_t r;   // low 16 = a, high 16 = b
    asm("cvt.rn.f16x2.f32 %0, %1, %2;" : "=r"(r) : "f"(b), "f"(a));
    return r;
}
__device__ __forceinline__ float2 unpack_h2(uint32_t p) {
    __half2 h = *reinterpret_cast<__half2*>(&p);
    return __half22float2(h);
}
__device__ __forceinline__ uint32_t swz(uint32_t o) { return o ^ ((o >> 3) & 0x70u); }

__device__ __forceinline__ void ldsm_x4(uint32_t* r, uint32_t addr) {
    asm volatile("ldmatrix.sync.aligned.m8n8.x4.shared.b16 {%0,%1,%2,%3}, [%4];"
                 : "=r"(r[0]), "=r"(r[1]), "=r"(r[2]), "=r"(r[3]) : "r"(addr));
}
__device__ __forceinline__ void mma_f16(float* d, const uint32_t* a, const uint32_t* b) {
    asm volatile("mma.sync.aligned.m16n8k16.row.col.f32.f16.f16.f32 "
                 "{%0,%1,%2,%3}, {%4,%5,%6,%7}, {%8,%9}, {%0,%1,%2,%3};"
                 : "+f"(d[0]), "+f"(d[1]), "+f"(d[2]), "+f"(d[3])
                 : "r"(a[0]), "r"(a[1]), "r"(a[2]), "r"(a[3]),
                   "r"(b[0]), "r"(b[1]));
}

// ---------------- smem layout (byte offsets from 128-aligned base) ----------
#define OFF_AH   0
#define OFF_AL   16384
#define OFF_BH   32768
#define OFF_BL   49152          // only 32 rows (tiles 12..15) -> 4 KB
#define OFF_BES  53248
#define OFF_CK   53760
#define OFF_SIDX 53888
#define OFF_LOSS 54400
#define SMEM_BYTES (54416 + 128)

// ---------------------------------------------------------------------------
// K0: setup — extended B (W_enc rows + cb@W_enc rows) scaled fp16 split,
//             recon table, ck consts, loss reset
// ---------------------------------------------------------------------------
__global__ void vq_setup_kernel(const float* __restrict__ W_enc,
                                const float* __restrict__ b_enc,
                                const float* __restrict__ codebook,
                                const float* __restrict__ W_dec,
                                const float* __restrict__ b_dec) {
    int g = blockIdx.x * 256 + threadIdx.x;            // 0 .. 131071
    {
        int n = g >> 10, k = g & 1023;
        float w = 0.f;
        if (n < LDIM) {
            w = W_enc[n * IDIM + k];
        } else if (n < LDIM + NCODES) {
            const float* cb = codebook + (n - LDIM) * LDIM;
#pragma unroll 20
            for (int j = 0; j < LDIM; ++j) w += cb[j] * W_enc[j * IDIM + k];
        }
        float ws = w * BSCALE;
        __half h = __float2half_rn(ws);
        g_Bh[g] = h;
        g_Bl[g] = __float2half_rn(ws - __half2float(h));
    }
    if (g < NCODES * IDIM) {
        int k = g >> 10, d = g & 1023;
        const float4* c4 = (const float4*)(codebook + k * LDIM);
        const float4* w4 = (const float4*)(W_dec + (size_t)d * LDIM);
        float s = b_dec[d];
#pragma unroll
        for (int j = 0; j < LDIM / 4; ++j) {
            float4 a = c4[j], b = w4[j];
            s += a.x * b.x + a.y * b.y + a.z * b.z + a.w * b.w;
        }
        g_recon[g] = s;
    }
    if (g < NCODES) {
        const float* c = codebook + g * LDIM;
        float cn = 0.f, bk = 0.f;
#pragma unroll 10
        for (int j = 0; j < LDIM; ++j) { cn += c[j] * c[j]; bk += b_enc[j] * c[j]; }
        g_ck[g] = cn - 2.f * bk;
    }
    if (g == 0) g_loss = 0.0;
}

// ---------------------------------------------------------------------------
// K1: main — HMMA scaled-fp16-split GEMM + fused argmin/loss/recon
// ---------------------------------------------------------------------------
extern __shared__ __align__(16) char dsm_raw[];

__global__ __launch_bounds__(256, 2)
void vq_main_kernel(const float* __restrict__ x,
                    const float* __restrict__ b_enc,
                    float* __restrict__ out_recon,
                    float* __restrict__ out_idx) {
    const int t = threadIdx.x;
    const int w = t >> 5, L = t & 31;
    const int row0 = blockIdx.x * CTA_M;

    uint32_t raw  = smem_u32(dsm_raw);
    uint32_t base = (raw + 127u) & ~127u;
    char* sm = dsm_raw + (base - raw);

    char* Ah = sm + OFF_AH;  char* Al = sm + OFF_AL;
    char* Bh = sm + OFF_BH;  char* Bl = sm + OFF_BL;
    float* bes   = (float*)(sm + OFF_BES);
    float* cks   = (float*)(sm + OFF_CK);
    int*   sidx  = (int*)  (sm + OFF_SIDX);
    float* sloss = (float*)(sm + OFF_LOSS);

    if (t < LDIM)   bes[t] = b_enc[t];
    if (t < NCODES) cks[t] = g_ck[t];
    if (t == 0)     *sloss = 0.f;

    float acc[NT][4];
#pragma unroll
    for (int j = 0; j < NT; ++j)
#pragma unroll
        for (int e = 0; e < 4; ++e) acc[j][e] = 0.f;

    const uint32_t mask  = (uint32_t)(L & 7) << 4;
    const uint32_t lowA0 = ((uint32_t)(L & 7) << 7) + ((uint32_t)(L >> 4) << 4);
    const uint32_t lowB4 = ((uint32_t)(L & 7) << 7) + ((uint32_t)((L >> 3) & 1) << 4)
                         + ((uint32_t)(L >> 4) << 10);
    const uint32_t aRow  = ((uint32_t)(w * 2 + ((L >> 3) & 1))) << 10;
    const uint32_t AhB = base + OFF_AH + aRow;
    const uint32_t AlB = base + OFF_AL + aRow;
    const uint32_t BhB = base + OFF_BH;
    const uint32_t BlB = base + OFF_BL - (12 << 10);   // tile j>=12 rebased

    // per-thread source coords
    const int xr = (t >> 4);          // row % 16 group
    const int xc = (t & 15) * 4;      // k offset (4 floats)

    // ---- prefetch chunk 0 of x into registers
    float4 xv[8];
#pragma unroll
    for (int it = 0; it < 8; ++it)
        xv[it] = *(const float4*)(x + (size_t)(row0 + it * 16 + xr) * IDIM + xc);

    for (int ch = 0; ch < NCHUNK; ++ch) {
        const int kc = ch * KC;
        __syncthreads();
        // ---- convert prefetched A: scaled (hi,lo) fp16 RN split, SW128 tiles
#pragma unroll
        for (int it = 0; it < 8; ++it) {
            float4 v = xv[it];
            int row = it * 16 + xr;
            float sx = v.x * ASCALE, sy = v.y * ASCALE;
            float sz = v.z * ASCALE, sw = v.w * ASCALE;
            uint32_t h01 = pack_f16x2(sx, sy);
            uint32_t h23 = pack_f16x2(sz, sw);
            float2 b01 = unpack_h2(h01), b23 = unpack_h2(h23);
            uint32_t l01 = pack_f16x2(sx - b01.x, sy - b01.y);
            uint32_t l23 = pack_f16x2(sz - b23.x, sw - b23.y);
            uint32_t off = swz((uint32_t)(row * 128 + xc * 2));
            *(uint2*)(Ah + off) = make_uint2(h01, h23);
            *(uint2*)(Al + off) = make_uint2(l01, l23);
        }
        // ---- stage Bh (128 rows) + Bl (rows 96..127 only), L2-hot
#pragma unroll
        for (int it = 0; it < 4; ++it) {
            int idx = it * 256 + t;                 // 0..1023
            int n = idx >> 3, k8 = (idx & 7) * 8;
            uint32_t off = swz((uint32_t)(n * 128 + k8 * 2));
            *(uint4*)(Bh + off) = *(const uint4*)(g_Bh + (size_t)n * IDIM + kc + k8);
        }
        {
            int n = t >> 3, k8 = (t & 7) * 8;       // n = 0..31
            uint32_t off = swz((uint32_t)(n * 128 + k8 * 2));
            *(uint4*)(Bl + off) = *(const uint4*)(g_Bl + (size_t)(96 + n) * IDIM + kc + k8);
        }
        __syncthreads();

        // ---- prefetch next chunk's x (latency hidden behind MMA below)
        if (ch + 1 < NCHUNK) {
            const float* xn = x + kc + KC + xc;
#pragma unroll
            for (int it = 0; it < 8; ++it)
                xv[it] = *(const float4*)(xn + (size_t)(row0 + it * 16 + xr) * IDIM);
        }

#pragma unroll
        for (int ks = 0; ks < 4; ++ks) {
            const uint32_t aoff = (lowA0 + (ks << 5)) ^ mask;
            const uint32_t boff = (lowB4 + (ks << 5)) ^ mask;
            uint32_t ah[4], al[4];
            ldsm_x4(ah, AhB + aoff);
            ldsm_x4(al, AlB + aoff);
#pragma unroll
            for (int j = 0; j < 12; j += 2) {       // z tiles: hh only
                uint32_t bh[4];
                ldsm_x4(bh, BhB + boff + (j << 10));
                mma_f16(acc[j],     ah, bh);
                mma_f16(acc[j + 1], ah, bh + 2);
            }
#pragma unroll
            for (int j = 12; j < 16; j += 2) {      // dot tiles: hh + lh + hl
                uint32_t bh[4], bl[4];
                ldsm_x4(bh, BhB + boff + (j << 10));
                ldsm_x4(bl, BlB + boff + (j << 10));
                mma_f16(acc[j],     ah, bh);
                mma_f16(acc[j],     al, bh);
                mma_f16(acc[j],     ah, bl);
                mma_f16(acc[j + 1], ah, bh + 2);
                mma_f16(acc[j + 1], al, bh + 2);
                mma_f16(acc[j + 1], ah, bl + 2);
            }
        }
    }

    // ---- epilogue (registers only). Thread owns rows (w*16+q, +8),
    //      cols 8j + 2*c0 + e, with c0 = L&3, q = L>>2. acc scaled by 2^18.
    const int c0 = L & 3;
    float zz0 = 0.f, zz1 = 0.f;
#pragma unroll
    for (int j = 0; j < 13; ++j) {
#pragma unroll
        for (int e = 0; e < 2; ++e) {
            int col = 8 * j + 2 * c0 + e;
            if (col < LDIM) {
                float b = bes[col];
                float z0 = fmaf(acc[j][e],     INVS, b);  zz0 += z0 * z0;
                float z1 = fmaf(acc[j][e + 2], INVS, b);  zz1 += z1 * z1;
            }
        }
    }
    float bd0 = 3.4e38f, bd1 = 3.4e38f;
    int   bk0 = NCODES,  bk1 = NCODES;
#pragma unroll
    for (int j = 12; j < NT; ++j) {
#pragma unroll
        for (int e = 0; e < 2; ++e) {
            int col = 8 * j + 2 * c0 + e;
            int k = col - LDIM;
            if (k >= 0 && k < NCODES) {
                float ckv = cks[k];
                float s0 = fmaf(acc[j][e],     -2.f * INVS, ckv);
                float s1 = fmaf(acc[j][e + 2], -2.f * INVS, ckv);
                if (s0 < bd0) { bd0 = s0; bk0 = k; }
                if (s1 < bd1) { bd1 = s1; bk1 = k; }
            }
        }
    }
#pragma unroll
    for (int off = 1; off < 4; off <<= 1) {
        float od0 = __shfl_xor_sync(0xffffffffu, bd0, off);
        int   ok0 = __shfl_xor_sync(0xffffffffu, bk0, off);
        float od1 = __shfl_xor_sync(0xffffffffu, bd1, off);
        int   ok1 = __shfl_xor_sync(0xffffffffu, bk1, off);
        zz0 += __shfl_xor_sync(0xffffffffu, zz0, off);
        zz1 += __shfl_xor_sync(0xffffffffu, zz1, off);
        if (od0 < bd0 || (od0 == bd0 && ok0 < bk0)) { bd0 = od0; bk0 = ok0; }
        if (od1 < bd1 || (od1 == bd1 && ok1 < bk1)) { bd1 = od1; bk1 = ok1; }
    }
    if (c0 == 0) {
        int q  = L >> 2;
        int r0 = w * 16 + q, r1 = r0 + 8;
        sidx[r0] = bk0;  sidx[r1] = bk1;
        out_idx[row0 + r0] = (float)bk0;
        out_idx[row0 + r1] = (float)bk1;
        atomicAdd(sloss, (zz0 + bd0) + (zz1 + bd1));
    }
    __syncthreads();
    if (t == 0) atomicAdd(&g_loss, (double)*sloss);

    // ---- fused recon gather (table L2-resident)
#pragma unroll 4
    for (int r = 0; r < CTA_M; ++r) {
        int k = sidx[r];
        float4 v = *(const float4*)(g_recon + (size_t)k * IDIM + t * 4);
        *(float4*)(out_recon + (size_t)(row0 + r) * IDIM + t * 4) = v;
    }
}

// ---------------------------------------------------------------------------
// K2: finalize loss
// ---------------------------------------------------------------------------
__global__ void vq_fin_kernel(float* __restrict__ out_loss, int M) {
    out_loss[0] = (float)(1.1 * g_loss / ((double)M * (double)LDIM));
}

extern "C" void kernel_launch(void* const* d_in, const int* in_sizes, int n_in,
                              void* d_out, int out_size) {
    const float* x        = (const float*)d_in[0];
    const float* W_enc    = (const float*)d_in[1];
    const float* b_enc    = (const float*)d_in[2];
    const float* codebook = (const float*)d_in[3];
    const float* W_dec    = (const float*)d_in[4];
    const float* b_dec    = (const float*)d_in[5];
    float* out = (float*)d_out;

    const int M = in_sizes[0] / IDIM;           // 65536
    float* out_recon = out;
    float* out_loss  = out + (size_t)M * IDIM;
    float* out_idx   = out_loss + 1;

    cudaFuncSetAttribute(vq_main_kernel,
                         cudaFuncAttributeMaxDynamicSharedMemorySize, SMEM_BYTES);

    vq_setup_kernel<<<(NPAD * IDIM) / 256, 256>>>(W_enc, b_enc, codebook, W_dec, b_dec);
    vq_main_kernel<<<M / CTA_M, 256, SMEM_BYTES>>>(x, b_enc, out_recon, out_idx);
    vq_fin_kernel<<<1, 1>>>(out_loss, M);
}

// round 11
// speedup vs baseline: 1.3801x; 1.3801x over previous
#include <cuda_runtime.h>
#include <cuda_fp16.h>
#include <cstdint>

// ---------------------------------------------------------------------------
// VQVAE forward on sm_103 (baseline PTX: ldmatrix + mma.sync fp16 + cp.async).
//   z_e = x @ W_enc^T + b_enc  via scaled fp16-split HMMA (fp32 accum)
//     A scaled 2^8, B scaled 2^10 -> residuals stay fp16-normal.
//     z tiles   (cols  0.. 95): 1 product  (hh)           (feeds loss mean only)
//     dot tiles (cols 96..127): 3 products (hh + lh + hl) fp32-level (argmin)
//   double-buffered smem; B staged with cp.async one chunk ahead;
//   x register-prefetched one chunk ahead; one syncthreads per chunk.
//   argmin / loss  : in-register epilogue + quad shfl reduce
//   x_recon        : fused coalesced gather from precomputed 21x1024 table
// ---------------------------------------------------------------------------

#define NCODES 21
#define LDIM   100
#define IDIM   1024
#define NPAD   128
#define CTA_M  128
#define KC     64
#define NCHUNK (IDIM / KC)
#define NT     16

#define ASCALE 256.0f                 // 2^8
#define BSCALE 1024.0f                // 2^10
#define INVS   3.814697265625e-06f    // 2^-18

__device__ __half g_Bh[NPAD * IDIM];
__device__ __half g_Bl[NPAD * IDIM];
__device__ float  g_recon[NCODES * IDIM];
__device__ float  g_ck[NCODES];            // ||c_k||^2 - 2 b.c_k
__device__ double g_loss;

__device__ __forceinline__ uint32_t smem_u32(const void* p) {
    uint32_t a;
    asm("{ .reg .u64 t; cvta.to.shared.u64 t, %1; cvt.u32.u64 %0, t; }"
        : "=r"(a) : "l"(p));
    return a;
}
__device__ __forceinline__ uint32_t pack_f16x2(float a, float b) {
    uint32_t r;   // low 16 = a, high 16 = b
    asm("cvt.rn.f16x2.f32 %0, %1, %2;" : "=r"(r) : "f"(b), "f"(a));
    return r;
}
__device__ __forceinline__ float2 unpack_h2(uint32_t p) {
    __half2 h = *reinterpret_cast<__half2*>(&p);
    return __half22float2(h);
}
__device__ __forceinline__ uint32_t swz(uint32_t o) { return o ^ ((o >> 3) & 0x70u); }

__device__ __forceinline__ void ldsm_x4(uint32_t* r, uint32_t addr) {
    asm volatile("ldmatrix.sync.aligned.m8n8.x4.shared.b16 {%0,%1,%2,%3}, [%4];"
                 : "=r"(r[0]), "=r"(r[1]), "=r"(r[2]), "=r"(r[3]) : "r"(addr));
}
__device__ __forceinline__ void mma_f16(float* d, const uint32_t* a, const uint32_t* b) {
    asm volatile("mma.sync.aligned.m16n8k16.row.col.f32.f16.f16.f32 "
                 "{%0,%1,%2,%3}, {%4,%5,%6,%7}, {%8,%9}, {%0,%1,%2,%3};"
                 : "+f"(d[0]), "+f"(d[1]), "+f"(d[2]), "+f"(d[3])
                 : "r"(a[0]), "r"(a[1]), "r"(a[2]), "r"(a[3]),
                   "r"(b[0]), "r"(b[1]));
}
#define CP_ASYNC16(dst, src) \
    asm volatile("cp.async.cg.shared.global [%0], [%1], 16;" \
                 :: "r"(dst), "l"(src) : "memory")
#define CP_COMMIT() asm volatile("cp.async.commit_group;" ::: "memory")
#define CP_WAIT0()  asm volatile("cp.async.wait_group 0;" ::: "memory")

// ---------------- smem layout: two 52KB buffers + consts ---------------------
#define BUF_STRIDE 53248
#define OFF_AH   0
#define OFF_AL   16384
#define OFF_BH   32768
#define OFF_BL   49152          // 32 rows (tiles 12..15) -> 4 KB
#define OFF_BES  106496
#define OFF_CK   107008
#define OFF_SIDX 107136
#define OFF_LOSS 107648
#define SMEM_BYTES (107664 + 128)

// ---------------------------------------------------------------------------
// K0: setup — extended B (W_enc rows + cb@W_enc rows) scaled fp16 split,
//             recon table, ck consts, loss reset
// ---------------------------------------------------------------------------
__global__ void vq_setup_kernel(const float* __restrict__ W_enc,
                                const float* __restrict__ b_enc,
                                const float* __restrict__ codebook,
                                const float* __restrict__ W_dec,
                                const float* __restrict__ b_dec) {
    int g = blockIdx.x * 256 + threadIdx.x;            // 0 .. 131071
    {
        int n = g >> 10, k = g & 1023;
        float w = 0.f;
        if (n < LDIM) {
            w = W_enc[n * IDIM + k];
        } else if (n < LDIM + NCODES) {
            const float* cb = codebook + (n - LDIM) * LDIM;
#pragma unroll 20
            for (int j = 0; j < LDIM; ++j) w += cb[j] * W_enc[j * IDIM + k];
        }
        float ws = w * BSCALE;
        __half h = __float2half_rn(ws);
        g_Bh[g] = h;
        g_Bl[g] = __float2half_rn(ws - __half2float(h));
    }
    if (g < NCODES * IDIM) {
        int k = g >> 10, d = g & 1023;
        const float4* c4 = (const float4*)(codebook + k * LDIM);
        const float4* w4 = (const float4*)(W_dec + (size_t)d * LDIM);
        float s = b_dec[d];
#pragma unroll
        for (int j = 0; j < LDIM / 4; ++j) {
            float4 a = c4[j], b = w4[j];
            s += a.x * b.x + a.y * b.y + a.z * b.z + a.w * b.w;
        }
        g_recon[g] = s;
    }
    if (g < NCODES) {
        const float* c = codebook + g * LDIM;
        float cn = 0.f, bk = 0.f;
#pragma unroll 10
        for (int j = 0; j < LDIM; ++j) { cn += c[j] * c[j]; bk += b_enc[j] * c[j]; }
        g_ck[g] = cn - 2.f * bk;
    }
    if (g == 0) g_loss = 0.0;
}

// ---------------------------------------------------------------------------
// K1: main — HMMA scaled-fp16-split GEMM + fused argmin/loss/recon
// ---------------------------------------------------------------------------
extern __shared__ __align__(16) char dsm_raw[];

__global__ __launch_bounds__(256, 2)
void vq_main_kernel(const float* __restrict__ x,
                    const float* __restrict__ b_enc,
                    float* __restrict__ out_recon,
                    float* __restrict__ out_idx) {
    const int t = threadIdx.x;
    const int w = t >> 5, L = t & 31;
    const int row0 = blockIdx.x * CTA_M;

    uint32_t raw  = smem_u32(dsm_raw);
    uint32_t base = (raw + 127u) & ~127u;
    char* sm = dsm_raw + (base - raw);

    float* bes   = (float*)(sm + OFF_BES);
    float* cks   = (float*)(sm + OFF_CK);
    int*   sidx  = (int*)  (sm + OFF_SIDX);
    float* sloss = (float*)(sm + OFF_LOSS);

    if (t < LDIM)   bes[t] = b_enc[t];
    if (t < NCODES) cks[t] = g_ck[t];
    if (t == 0)     *sloss = 0.f;

    float acc[NT][4];
#pragma unroll
    for (int j = 0; j < NT; ++j)
#pragma unroll
        for (int e = 0; e < 4; ++e) acc[j][e] = 0.f;

    const uint32_t mask  = (uint32_t)(L & 7) << 4;
    const uint32_t lowA0 = ((uint32_t)(L & 7) << 7) + ((uint32_t)(L >> 4) << 4);
    const uint32_t lowB4 = ((uint32_t)(L & 7) << 7) + ((uint32_t)((L >> 3) & 1) << 4)
                         + ((uint32_t)(L >> 4) << 10);
    const uint32_t aRow  = ((uint32_t)(w * 2 + ((L >> 3) & 1))) << 10;

    // per-thread source coords
    const int xr = (t >> 4);          // row group within 16
    const int xc = (t & 15) * 4;      // k offset (4 floats)

    // staging coords (B)
    const int sb_n  = t >> 3;                 // 0..31
    const int sb_k8 = (t & 7) * 8;

    // ---- helpers as lambdas -------------------------------------------------
    auto stageB = [&](int ch, int buf) {
        const int kc = ch * KC;
        uint32_t bOff = base + buf * BUF_STRIDE;
#pragma unroll
        for (int it = 0; it < 4; ++it) {
            int n = it * 32 + sb_n;
            uint32_t dst = bOff + OFF_BH + swz((uint32_t)(n * 128 + sb_k8 * 2));
            CP_ASYNC16(dst, (const void*)(g_Bh + (size_t)n * IDIM + kc + sb_k8));
        }
        {
            uint32_t dst = bOff + OFF_BL + swz((uint32_t)(sb_n * 128 + sb_k8 * 2));
            CP_ASYNC16(dst, (const void*)(g_Bl + (size_t)(96 + sb_n) * IDIM + kc + sb_k8));
        }
        CP_COMMIT();
    };
    auto convertA = [&](const float4* xv, int buf) {
        char* Ah = sm + buf * BUF_STRIDE + OFF_AH;
        char* Al = sm + buf * BUF_STRIDE + OFF_AL;
#pragma unroll
        for (int it = 0; it < 8; ++it) {
            float4 v = xv[it];
            int row = it * 16 + xr;
            float sx = v.x * ASCALE, sy = v.y * ASCALE;
            float sz = v.z * ASCALE, sw = v.w * ASCALE;
            uint32_t h01 = pack_f16x2(sx, sy);
            uint32_t h23 = pack_f16x2(sz, sw);
            float2 b01 = unpack_h2(h01), b23 = unpack_h2(h23);
            uint32_t l01 = pack_f16x2(sx - b01.x, sy - b01.y);
            uint32_t l23 = pack_f16x2(sz - b23.x, sw - b23.y);
            uint32_t off = swz((uint32_t)(row * 128 + xc * 2));
            *(uint2*)(Ah + off) = make_uint2(h01, h23);
            *(uint2*)(Al + off) = make_uint2(l01, l23);
        }
    };

    // ---- prologue: chunk 0 staged synchronously
    float4 xv[8];
#pragma unroll
    for (int it = 0; it < 8; ++it)
        xv[it] = *(const float4*)(x + (size_t)(row0 + it * 16 + xr) * IDIM + xc);
    stageB(0, 0);
    convertA(xv, 0);
    CP_WAIT0();
    __syncthreads();

    for (int ch = 0; ch < NCHUNK; ++ch) {
        const int buf  = ch & 1;
        const int nbuf = buf ^ 1;
        const uint32_t bufAdd = (uint32_t)(buf * BUF_STRIDE);
        const uint32_t AhB = base + bufAdd + OFF_AH + aRow;
        const uint32_t AlB = base + bufAdd + OFF_AL + aRow;
        const uint32_t BhB = base + bufAdd + OFF_BH;
        const uint32_t BlB = base + bufAdd + OFF_BL - (12 << 10);

        const bool more = (ch + 1 < NCHUNK);
        if (more) {
            // prefetch next x into regs + async-stage next B (hidden by MMAs)
            const float* xn = x + (ch + 1) * KC + xc;
#pragma unroll
            for (int it = 0; it < 8; ++it)
                xv[it] = *(const float4*)(xn + (size_t)(row0 + it * 16 + xr) * IDIM);
            stageB(ch + 1, nbuf);
        }

#pragma unroll
        for (int ks = 0; ks < 4; ++ks) {
            const uint32_t aoff = (lowA0 + (ks << 5)) ^ mask;
            const uint32_t boff = (lowB4 + (ks << 5)) ^ mask;
            uint32_t ah[4], al[4];
            ldsm_x4(ah, AhB + aoff);
            ldsm_x4(al, AlB + aoff);
#pragma unroll
            for (int j = 0; j < 12; j += 2) {       // z tiles: hh only
                uint32_t bh[4];
                ldsm_x4(bh, BhB + boff + (j << 10));
                mma_f16(acc[j],     ah, bh);
                mma_f16(acc[j + 1], ah, bh + 2);
            }
#pragma unroll
            for (int j = 12; j < 16; j += 2) {      // dot tiles: hh + lh + hl
                uint32_t bh[4], bl[4];
                ldsm_x4(bh, BhB + boff + (j << 10));
                ldsm_x4(bl, BlB + boff + (j << 10));
                mma_f16(acc[j],     ah, bh);
                mma_f16(acc[j],     al, bh);
                mma_f16(acc[j],     ah, bl);
                mma_f16(acc[j + 1], ah, bh + 2);
                mma_f16(acc[j + 1], al, bh + 2);
                mma_f16(acc[j + 1], ah, bl + 2);
            }
        }

        if (more) {
            convertA(xv, nbuf);       // xv LDG latency was hidden by MMAs
            CP_WAIT0();
            __syncthreads();
        }
    }

    // ---- epilogue (registers only). Thread owns rows (w*16+q, +8),
    //      cols 8j + 2*c0 + e, with c0 = L&3, q = L>>2. acc scaled by 2^18.
    const int c0 = L & 3;
    float zz0 = 0.f, zz1 = 0.f;
#pragma unroll
    for (int j = 0; j < 13; ++j) {
#pragma unroll
        for (int e = 0; e < 2; ++e) {
            int col = 8 * j + 2 * c0 + e;
            if (col < LDIM) {
                float b = bes[col];
                float z0 = fmaf(acc[j][e],     INVS, b);  zz0 += z0 * z0;
                float z1 = fmaf(acc[j][e + 2], INVS, b);  zz1 += z1 * z1;
            }
        }
    }
    float bd0 = 3.4e38f, bd1 = 3.4e38f;
    int   bk0 = NCODES,  bk1 = NCODES;
#pragma unroll
    for (int j = 12; j < NT; ++j) {
#pragma unroll
        for (int e = 0; e < 2; ++e) {
            int col = 8 * j + 2 * c0 + e;
            int k = col - LDIM;
            if (k >= 0 && k < NCODES) {
                float ckv = cks[k];
                float s0 = fmaf(acc[j][e],     -2.f * INVS, ckv);
                float s1 = fmaf(acc[j][e + 2], -2.f * INVS, ckv);
                if (s0 < bd0) { bd0 = s0; bk0 = k; }
                if (s1 < bd1) { bd1 = s1; bk1 = k; }
            }
        }
    }
#pragma unroll
    for (int off = 1; off < 4; off <<= 1) {
        float od0 = __shfl_xor_sync(0xffffffffu, bd0, off);
        int   ok0 = __shfl_xor_sync(0xffffffffu, bk0, off);
        float od1 = __shfl_xor_sync(0xffffffffu, bd1, off);
        int   ok1 = __shfl_xor_sync(0xffffffffu, bk1, off);
        zz0 += __shfl_xor_sync(0xffffffffu, zz0, off);
        zz1 += __shfl_xor_sync(0xffffffffu, zz1, off);
        if (od0 < bd0 || (od0 == bd0 && ok0 < bk0)) { bd0 = od0; bk0 = ok0; }
        if (od1 < bd1 || (od1 == bd1 && ok1 < bk1)) { bd1 = od1; bk1 = ok1; }
    }
    __syncthreads();              // acc/ldsm done; reuse barrier before sidx
    if (c0 == 0) {
        int q  = L >> 2;
        int r0 = w * 16 + q, r1 = r0 + 8;
        sidx[r0] = bk0;  sidx[r1] = bk1;
        out_idx[row0 + r0] = (float)bk0;
        out_idx[row0 + r1] = (float)bk1;
        atomicAdd(sloss, (zz0 + bd0) + (zz1 + bd1));
    }
    __syncthreads();
    if (t == 0) atomicAdd(&g_loss, (double)*sloss);

    // ---- fused recon gather (table L2-resident)
#pragma unroll 4
    for (int r = 0; r < CTA_M; ++r) {
        int k = sidx[r];
        float4 v = *(const float4*)(g_recon + (size_t)k * IDIM + t * 4);
        *(float4*)(out_recon + (size_t)(row0 + r) * IDIM + t * 4) = v;
    }
}

// ---------------------------------------------------------------------------
// K2: finalize loss
// ---------------------------------------------------------------------------
__global__ void vq_fin_kernel(float* __restrict__ out_loss, int M) {
    out_loss[0] = (float)(1.1 * g_loss / ((double)M * (double)LDIM));
}

extern "C" void kernel_launch(void* const* d_in, const int* in_sizes, int n_in,
                              void* d_out, int out_size) {
    const float* x        = (const float*)d_in[0];
    const float* W_enc    = (const float*)d_in[1];
    const float* b_enc    = (const float*)d_in[2];
    const float* codebook = (const float*)d_in[3];
    const float* W_dec    = (const float*)d_in[4];
    const float* b_dec    = (const float*)d_in[5];
    float* out = (float*)d_out;

    const int M = in_sizes[0] / IDIM;           // 65536
    float* out_recon = out;
    float* out_loss  = out + (size_t)M * IDIM;
    float* out_idx   = out_loss + 1;

    cudaFuncSetAttribute(vq_main_kernel,
                         cudaFuncAttributeMaxDynamicSharedMemorySize, SMEM_BYTES);

    vq_setup_kernel<<<(NPAD * IDIM) / 256, 256>>>(W_enc, b_enc, codebook, W_dec, b_dec);
    vq_main_kernel<<<M / CTA_M, 256, SMEM_BYTES>>>(x, b_enc, out_recon, out_idx);
    vq_fin_kernel<<<1, 1>>>(out_loss, M);
}